// round 5
// baseline (speedup 1.0000x reference)
#include <cuda_runtime.h>

#define H 1024
#define S 65536
#define RPB 8                       // rows per block in GEMV (1 row per warp)
#define GEMV_GRID (S / RPB)         // 8192 blocks
#define K1_CHUNKS 32                // i-chunks of 32 rows
#define K1_GRID (K1_CHUNKS + 1)     // + one block for b.h
#define FIN_BLOCKS 256
#define FIN_TPB 256

// ---- scratch (device globals; no allocation anywhere) ----
__device__ float g_vpart[K1_CHUNKS * H];   // per-chunk partials of v = W^T h
__device__ float g_v[H];                   // reduced v
__device__ float g_bh;                     // b . h
__device__ float g_bm[GEMV_GRID];          // per-block score max
__device__ float g_bs[GEMV_GRID];          // per-block sum of exp(s - m_b)
__device__ unsigned g_ctr1;                // last-block counter (self-resetting)

// ---------------------------------------------------------------------------
// K1: v = W^T h (+ b.h). 32 compute blocks x 1024 threads.
// Block = 32-row i-chunk. Thread (rg=t>>8, jt=t&255): 8 front-batched LDG.128
// over rows i0+4k+rg, columns 4*jt..4*jt+3. 4-way rg-reduce in shared.
// Last finished block reduces the 32 chunk-partials -> g_v.
// ---------------------------------------------------------------------------
__global__ __launch_bounds__(1024) void k1_prep(const float* __restrict__ hidden,
                                                const float* __restrict__ W,
                                                const float* __restrict__ b) {
    __shared__ float4 red[1024];        // 16 KB cross-rg reduce
    __shared__ float  hs[32];
    int t = threadIdx.x;

    if (blockIdx.x < K1_CHUNKS) {
        int rg = t >> 8;                // row-group 0..3
        int jt = t & 255;               // float4 column
        int i0 = blockIdx.x * 32;

        if (t < 32) hs[t] = hidden[i0 + t];
        __syncthreads();

        const float4* Wp = (const float4*)W + jt;   // row stride = 256 float4
        float4 a[8];
#pragma unroll
        for (int k = 0; k < 8; k++)                  // 8 independent LDG.128
            a[k] = Wp[(size_t)(i0 + 4 * k + rg) * (H / 4)];

        float4 acc = make_float4(0.f, 0.f, 0.f, 0.f);
#pragma unroll
        for (int k = 0; k < 8; k++) {
            float hv = hs[4 * k + rg];
            acc.x = fmaf(a[k].x, hv, acc.x);
            acc.y = fmaf(a[k].y, hv, acc.y);
            acc.z = fmaf(a[k].z, hv, acc.z);
            acc.w = fmaf(a[k].w, hv, acc.w);
        }
        red[t] = acc;
        __syncthreads();
        if (rg == 0) {
            float4 r0 = red[jt], r1 = red[jt + 256],
                   r2 = red[jt + 512], r3 = red[jt + 768];
            r0.x += r1.x + r2.x + r3.x;
            r0.y += r1.y + r2.y + r3.y;
            r0.z += r1.z + r2.z + r3.z;
            r0.w += r1.w + r2.w + r3.w;
            ((float4*)(g_vpart + blockIdx.x * H))[jt] = r0;
        }
    } else {
        // b . h with one 1024-thread block
        float* s = (float*)red;         // reuse shared
        s[t] = b[t] * hidden[t];
        __syncthreads();
        for (int o = 512; o; o >>= 1) {
            if (t < o) s[t] += s[t + o];
            __syncthreads();
        }
        if (t == 0) g_bh = s[0];
    }

    // last-block-done: fold the chunk reduction into this launch
    __threadfence();
    __shared__ bool isLast;
    if (t == 0) {
        unsigned c = atomicAdd(&g_ctr1, 1u);
        isLast = (c == K1_GRID - 1);
        if (isLast) g_ctr1 = 0;         // reset for graph replay
    }
    __syncthreads();
    if (isLast) {
        __threadfence();
        float a0 = 0.f, a1 = 0.f, a2 = 0.f, a3 = 0.f;   // 4 independent chains
#pragma unroll
        for (int c = 0; c < K1_CHUNKS; c += 4) {
            a0 += g_vpart[(c + 0) * H + t];
            a1 += g_vpart[(c + 1) * H + t];
            a2 += g_vpart[(c + 2) * H + t];
            a3 += g_vpart[(c + 3) * H + t];
        }
        g_v[t] = (a0 + a1) + (a2 + a3);
    }
}

// ---------------------------------------------------------------------------
// K2: streaming GEMV + partial softmax.
// 1 warp per row, 8x front-batched LDG.128 (evict-first), v staged in shared.
// Per block: out[row] = exp(score - m_b); store (m_b, sum_b).
// ---------------------------------------------------------------------------
__global__ __launch_bounds__(256) void k2_gemv(const float* __restrict__ enc,
                                               float* __restrict__ out) {
    __shared__ float4 sv[H / 4];        // 4 KB
    sv[threadIdx.x] = ((const float4*)g_v)[threadIdx.x];
    __syncthreads();

    int warp = threadIdx.x >> 5;
    int lane = threadIdx.x & 31;
    int row  = blockIdx.x * RPB + warp;
    const float4* rp = (const float4*)(enc + (size_t)row * H);

    float4 a[8];
#pragma unroll
    for (int k = 0; k < 8; k++) a[k] = __ldcs(rp + lane + 32 * k);   // MLP=8

    float acc = 0.f;
#pragma unroll
    for (int k = 0; k < 8; k++) {
        float4 vv = sv[lane + 32 * k];
        acc = fmaf(a[k].x, vv.x, acc);
        acc = fmaf(a[k].y, vv.y, acc);
        acc = fmaf(a[k].z, vv.z, acc);
        acc = fmaf(a[k].w, vv.w, acc);
    }
#pragma unroll
    for (int o = 16; o; o >>= 1) acc += __shfl_xor_sync(0xFFFFFFFFu, acc, o);

    __shared__ float ws[RPB];
    if (lane == 0) ws[warp] = acc + g_bh;
    __syncthreads();

    if (threadIdx.x == 0) {
        float mb = ws[0];
#pragma unroll
        for (int i = 1; i < RPB; i++) mb = fmaxf(mb, ws[i]);
        float sm = 0.f;
#pragma unroll
        for (int i = 0; i < RPB; i++) {
            float e = expf(ws[i] - mb);
            sm += e;
            out[blockIdx.x * RPB + i] = e;
        }
        g_bm[blockIdx.x] = mb;
        g_bs[blockIdx.x] = sm;
    }
}

// ---------------------------------------------------------------------------
// K3: finalize. Each block redundantly reduces the 8192 (m_b, sum_b) pairs
// (L2-resident, fixed order -> deterministic), then rescales its 256 outputs:
//   out[i] *= exp(m_b(i) - gmax) / total
// ---------------------------------------------------------------------------
__global__ __launch_bounds__(FIN_TPB) void k3_finalize(float* __restrict__ out) {
    __shared__ float s[FIN_TPB];
    int t = threadIdx.x;

    float m = -3.4e38f;
#pragma unroll
    for (int k = 0; k < GEMV_GRID / FIN_TPB; k++)
        m = fmaxf(m, g_bm[t + FIN_TPB * k]);
    s[t] = m;
    __syncthreads();
    for (int o = FIN_TPB / 2; o; o >>= 1) {
        if (t < o) s[t] = fmaxf(s[t], s[t + o]);
        __syncthreads();
    }
    float gmax = s[0];
    __syncthreads();

    float sm = 0.f;
#pragma unroll
    for (int k = 0; k < GEMV_GRID / FIN_TPB; k++) {
        int idx = t + FIN_TPB * k;
        sm += g_bs[idx] * expf(g_bm[idx] - gmax);
    }
    s[t] = sm;
    __syncthreads();
    for (int o = FIN_TPB / 2; o; o >>= 1) {
        if (t < o) s[t] += s[t + o];
        __syncthreads();
    }
    float inv = 1.0f / s[0];

    int i = blockIdx.x * FIN_TPB + t;
    out[i] = out[i] * expf(g_bm[i >> 3] - gmax) * inv;
}

extern "C" void kernel_launch(void* const* d_in, const int* in_sizes, int n_in,
                              void* d_out, int out_size) {
    const float* hidden = (const float*)d_in[0];   // [1024]
    const float* enc    = (const float*)d_in[1];   // [65536, 1024]
    const float* W      = (const float*)d_in[2];   // [1024, 1024]
    const float* b      = (const float*)d_in[3];   // [1024]
    float* out = (float*)d_out;                    // [65536]

    k1_prep<<<K1_GRID, 1024>>>(hidden, W, b);
    k2_gemv<<<GEMV_GRID, 256>>>(enc, out);
    k3_finalize<<<FIN_BLOCKS, FIN_TPB>>>(out);
}

// round 6
// speedup vs baseline: 1.0494x; 1.0494x over previous
#include <cuda_runtime.h>

#define H 1024
#define S 65536
#define RPB 8                       // rows per block in GEMV (1 row per warp)
#define GEMV_GRID (S / RPB)         // 8192 blocks
#define FIN_BLOCKS 256
#define FIN_TPB 256

// ---- scratch (device globals; no allocation anywhere) ----
__device__ float g_v[H];                   // v = W^T h
__device__ float g_bh;                     // b . h
__device__ float g_bm[GEMV_GRID];          // per-block score max
__device__ float g_bs[GEMV_GRID];          // per-block sum of exp(s - m_b)

// ---------------------------------------------------------------------------
// K1: v = W^T h (+ b.h). 32 W-blocks x 1024 threads; block b fully owns
// columns 32b..32b+31 (no cross-block reduce, no fence, no atomics).
// Thread (chunk=t>>5, lane=t&31): col j = 32b+lane, rows chunk*32..+31,
// loaded in 4 batches of 8 independent scalar LDGs (MLP=8, low reg pressure).
// Warp load = 128B contiguous. Chunk partials reduced via padded SMEM tile.
// Block 32 computes b.h.
// ---------------------------------------------------------------------------
__global__ __launch_bounds__(1024) void k1_prep(const float* __restrict__ hidden,
                                                const float* __restrict__ W,
                                                const float* __restrict__ b) {
    __shared__ float hs[H];
    __shared__ float red[32 * 33];          // padded: chunk-major, +1 to kill conflicts
    int t = threadIdx.x;

    if (blockIdx.x < 32) {
        hs[t] = hidden[t];
        __syncthreads();

        int lane  = t & 31;
        int chunk = t >> 5;
        int j  = blockIdx.x * 32 + lane;
        int r0 = chunk * 32;
        const float* Wp = W + (size_t)r0 * H + j;

        float acc = 0.f;
#pragma unroll
        for (int rb = 0; rb < 32; rb += 8) {
            float a0 = Wp[(size_t)(rb + 0) * H];
            float a1 = Wp[(size_t)(rb + 1) * H];
            float a2 = Wp[(size_t)(rb + 2) * H];
            float a3 = Wp[(size_t)(rb + 3) * H];
            float a4 = Wp[(size_t)(rb + 4) * H];
            float a5 = Wp[(size_t)(rb + 5) * H];
            float a6 = Wp[(size_t)(rb + 6) * H];
            float a7 = Wp[(size_t)(rb + 7) * H];
            acc = fmaf(a0, hs[r0 + rb + 0], acc);
            acc = fmaf(a1, hs[r0 + rb + 1], acc);
            acc = fmaf(a2, hs[r0 + rb + 2], acc);
            acc = fmaf(a3, hs[r0 + rb + 3], acc);
            acc = fmaf(a4, hs[r0 + rb + 4], acc);
            acc = fmaf(a5, hs[r0 + rb + 5], acc);
            acc = fmaf(a6, hs[r0 + rb + 6], acc);
            acc = fmaf(a7, hs[r0 + rb + 7], acc);
        }
        red[chunk * 33 + lane] = acc;
        __syncthreads();

        if (t < 32) {                        // one thread per owned column
            float s0 = 0.f, s1 = 0.f, s2 = 0.f, s3 = 0.f;
#pragma unroll
            for (int c = 0; c < 32; c += 4) {
                s0 += red[(c + 0) * 33 + t];
                s1 += red[(c + 1) * 33 + t];
                s2 += red[(c + 2) * 33 + t];
                s3 += red[(c + 3) * 33 + t];
            }
            g_v[blockIdx.x * 32 + t] = (s0 + s1) + (s2 + s3);
        }
    } else {
        // b . h
        float* s = red;
        s[t] = b[t] * hidden[t];
        __syncthreads();
        for (int o = 512; o >= 32; o >>= 1) {
            if (t < o) s[t] += s[t + o];
            __syncthreads();
        }
        if (t < 32) {
            float v = s[t];
#pragma unroll
            for (int o = 16; o; o >>= 1) v += __shfl_xor_sync(0xFFFFFFFFu, v, o);
            if (t == 0) g_bh = v;
        }
    }
}

// ---------------------------------------------------------------------------
// K2: streaming GEMV + partial softmax.
// 1 warp per row, 8x front-batched LDG.128 (evict-first), v staged in shared.
// Per block: out[row] = exp(score - m_b); store (m_b, sum_b).
// ---------------------------------------------------------------------------
__global__ __launch_bounds__(256) void k2_gemv(const float* __restrict__ enc,
                                               float* __restrict__ out) {
    __shared__ float4 sv[H / 4];        // 4 KB
    sv[threadIdx.x] = ((const float4*)g_v)[threadIdx.x];
    __syncthreads();

    int warp = threadIdx.x >> 5;
    int lane = threadIdx.x & 31;
    int row  = blockIdx.x * RPB + warp;
    const float4* rp = (const float4*)(enc + (size_t)row * H);

    float4 a[8];
#pragma unroll
    for (int k = 0; k < 8; k++) a[k] = __ldcs(rp + lane + 32 * k);   // MLP=8

    float acc = 0.f;
#pragma unroll
    for (int k = 0; k < 8; k++) {
        float4 vv = sv[lane + 32 * k];
        acc = fmaf(a[k].x, vv.x, acc);
        acc = fmaf(a[k].y, vv.y, acc);
        acc = fmaf(a[k].z, vv.z, acc);
        acc = fmaf(a[k].w, vv.w, acc);
    }
#pragma unroll
    for (int o = 16; o; o >>= 1) acc += __shfl_xor_sync(0xFFFFFFFFu, acc, o);

    __shared__ float ws[RPB];
    if (lane == 0) ws[warp] = acc + g_bh;
    __syncthreads();

    if (threadIdx.x == 0) {
        float mb = ws[0];
#pragma unroll
        for (int i = 1; i < RPB; i++) mb = fmaxf(mb, ws[i]);
        float sm = 0.f;
#pragma unroll
        for (int i = 0; i < RPB; i++) {
            float e = expf(ws[i] - mb);
            sm += e;
            out[blockIdx.x * RPB + i] = e;
        }
        g_bm[blockIdx.x] = mb;
        g_bs[blockIdx.x] = sm;
    }
}

// ---------------------------------------------------------------------------
// K3: finalize. Each block redundantly reduces the 8192 (m_b, sum_b) pairs
// (L2-resident, fixed order -> deterministic), then rescales its 256 outputs:
//   out[i] *= exp(m_b(i) - gmax) / total
// ---------------------------------------------------------------------------
__global__ __launch_bounds__(FIN_TPB) void k3_finalize(float* __restrict__ out) {
    __shared__ float s[FIN_TPB];
    int t = threadIdx.x;

    float m = -3.4e38f;
#pragma unroll
    for (int k = 0; k < GEMV_GRID / FIN_TPB; k++)
        m = fmaxf(m, g_bm[t + FIN_TPB * k]);
    s[t] = m;
    __syncthreads();
    for (int o = FIN_TPB / 2; o; o >>= 1) {
        if (t < o) s[t] = fmaxf(s[t], s[t + o]);
        __syncthreads();
    }
    float gmax = s[0];
    __syncthreads();

    float sm = 0.f;
#pragma unroll
    for (int k = 0; k < GEMV_GRID / FIN_TPB; k++) {
        int idx = t + FIN_TPB * k;
        sm += g_bs[idx] * expf(g_bm[idx] - gmax);
    }
    s[t] = sm;
    __syncthreads();
    for (int o = FIN_TPB / 2; o; o >>= 1) {
        if (t < o) s[t] += s[t + o];
        __syncthreads();
    }
    float inv = 1.0f / s[0];

    int i = blockIdx.x * FIN_TPB + t;
    out[i] = out[i] * expf(g_bm[i >> 3] - gmax) * inv;
}

extern "C" void kernel_launch(void* const* d_in, const int* in_sizes, int n_in,
                              void* d_out, int out_size) {
    const float* hidden = (const float*)d_in[0];   // [1024]
    const float* enc    = (const float*)d_in[1];   // [65536, 1024]
    const float* W      = (const float*)d_in[2];   // [1024, 1024]
    const float* b      = (const float*)d_in[3];   // [1024]
    float* out = (float*)d_out;                    // [65536]

    k1_prep<<<33, 1024>>>(hidden, W, b);
    k2_gemv<<<GEMV_GRID, 256>>>(enc, out);
    k3_finalize<<<FIN_BLOCKS, FIN_TPB>>>(out);
}